// round 6
// baseline (speedup 1.0000x reference)
#include <cuda_runtime.h>
#include <cuda_bf16.h>
#include <stdint.h>
#include <math.h>

// Problem constants
#define BB 2
#define TT 2048
#define CC 2048
#define NHH 16
#define HDD 128
#define MTOK (BB*TT)        // 4096
#define THREEC (3*CC)       // 6144

// ---------------- scratch (device globals) ----------------
__device__ float g_qkv[(size_t)MTOK * THREEC];
__device__ float g_y[(size_t)MTOK * CC];
__device__ int8_t g_w8a[(size_t)THREEC * CC];
__device__ int8_t g_w8p[(size_t)CC * CC];
__device__ int8_t g_x1[(size_t)MTOK * CC];
__device__ int8_t g_x2[(size_t)MTOK * CC];
__device__ float  g_sx[MTOK];
__device__ int8_t g_y1[(size_t)MTOK * CC];
__device__ int8_t g_y2[(size_t)MTOK * CC];
__device__ float  g_sy[MTOK];
__device__ __nv_bfloat16 g_qhi[(size_t)BB*NHH*TT*HDD];
__device__ __nv_bfloat16 g_qlo[(size_t)BB*NHH*TT*HDD];
__device__ __nv_bfloat16 g_khi[(size_t)BB*NHH*TT*HDD];
__device__ __nv_bfloat16 g_klo[(size_t)BB*NHH*TT*HDD];
__device__ __nv_bfloat16 g_vhi[(size_t)BB*NHH*TT*HDD];
__device__ __nv_bfloat16 g_vlo[(size_t)BB*NHH*TT*HDD];

// ===================== helpers =====================
__device__ __forceinline__ uint32_t smem_u32(const void* p) {
    uint32_t a;
    asm("{ .reg .u64 t; cvta.to.shared.u64 t, %1; cvt.u32.u64 %0, t; }" : "=r"(a) : "l"(p));
    return a;
}
#define CP_ASYNC16(s, g) asm volatile("cp.async.cg.shared.global [%0], [%1], 16;" :: "r"(s), "l"(g))
#define CP_COMMIT()      asm volatile("cp.async.commit_group;" ::: "memory")
#define CP_WAIT(n)       asm volatile("cp.async.wait_group %0;" :: "n"(n) : "memory")

__device__ __forceinline__ void ldm_x4(uint32_t& r0, uint32_t& r1, uint32_t& r2, uint32_t& r3,
                                       uint32_t addr) {
    asm volatile("ldmatrix.sync.aligned.m8n8.x4.shared.b16 {%0,%1,%2,%3}, [%4];"
                 : "=r"(r0), "=r"(r1), "=r"(r2), "=r"(r3) : "r"(addr));
}
__device__ __forceinline__ void ldm_x4_t(uint32_t& r0, uint32_t& r1, uint32_t& r2, uint32_t& r3,
                                         uint32_t addr) {
    asm volatile("ldmatrix.sync.aligned.m8n8.x4.trans.shared.b16 {%0,%1,%2,%3}, [%4];"
                 : "=r"(r0), "=r"(r1), "=r"(r2), "=r"(r3) : "r"(addr));
}
__device__ __forceinline__ void mma_bf16(float* c, const uint32_t* a, uint32_t b0, uint32_t b1) {
    asm volatile(
        "mma.sync.aligned.m16n8k16.row.col.f32.bf16.bf16.f32 "
        "{%0,%1,%2,%3}, {%4,%5,%6,%7}, {%8,%9}, {%0,%1,%2,%3};"
        : "+f"(c[0]), "+f"(c[1]), "+f"(c[2]), "+f"(c[3])
        : "r"(a[0]), "r"(a[1]), "r"(a[2]), "r"(a[3]), "r"(b0), "r"(b1));
}
__device__ __forceinline__ void mma_s8(int* c, const uint32_t* a, uint32_t b0, uint32_t b1) {
    asm volatile(
        "mma.sync.aligned.m16n8k32.row.col.s32.s8.s8.s32 "
        "{%0,%1,%2,%3}, {%4,%5,%6,%7}, {%8,%9}, {%0,%1,%2,%3};"
        : "+r"(c[0]), "+r"(c[1]), "+r"(c[2]), "+r"(c[3])
        : "r"(a[0]), "r"(a[1]), "r"(a[2]), "r"(a[3]), "r"(b0), "r"(b1));
}

// ===================== int8 IMMA GEMM =====================
// out[m,n] = sA[m] * wscale[n] * (128 * A1@W + A2@W)  (all s8, int32 accum)
// Tile 128x128, K-chunk 64 bytes, 8 warps (2x4), 3-stage cp.async pipeline.
#define BM 128
#define BN 128
#define PKB 80                    // smem row pitch bytes (64 data + 16 pad)
#define STG_B (BM * PKB)          // 10240 bytes per stage per matrix
#define NSTG 3
#define GEMM_SMEM (NSTG * STG_B * 2)   // 61440 bytes

__global__ __launch_bounds__(256) void gemm_imma(
    const int8_t* __restrict__ A1, const int8_t* __restrict__ A2,
    const int8_t* __restrict__ W8, const float* __restrict__ sA,
    const float* __restrict__ wscale, float* __restrict__ out, int Ndim, int Kdim)
{
    extern __shared__ int8_t smg[];
    const uint32_t sbA = smem_u32(smg);
    const uint32_t sbB = sbA + NSTG * STG_B;

    const int tid = threadIdx.x, lane = tid & 31, wid = tid >> 5;
    const int wm = (wid >> 2) * 64;
    const int wn = (wid & 3) * 32;
    const int m0 = blockIdx.y * BM;
    const int n0 = blockIdx.x * BN;
    const int KHALF = Kdim >> 6;      // 64-byte chunks per pass
    const int KC = 2 * KHALF;

    int c[4][4][4];
#pragma unroll
    for (int i = 0; i < 4; i++)
#pragma unroll
        for (int j = 0; j < 4; j++)
#pragma unroll
            for (int q = 0; q < 4; q++) c[i][j][q] = 0;

    const int lr = tid >> 2;          // 0..63
    const int lq = (tid & 3) * 16;    // byte col 0,16,32,48

    auto load_stage = [&](int kc, int s) {
        const int8_t* Ap = (kc < KHALF) ? A1 : A2;
        const int k0 = (kc % KHALF) << 6;
#pragma unroll
        for (int half = 0; half < 2; half++) {
            int r = lr + half * 64;
            CP_ASYNC16(sbA + (uint32_t)(s * STG_B + r * PKB + lq),
                       Ap + (size_t)(m0 + r) * Kdim + k0 + lq);
            CP_ASYNC16(sbB + (uint32_t)(s * STG_B + r * PKB + lq),
                       W8 + (size_t)(n0 + r) * Kdim + k0 + lq);
        }
    };

#pragma unroll
    for (int s = 0; s < NSTG - 1; s++) { load_stage(s, s); CP_COMMIT(); }

    for (int kc = 0; kc < KC; kc++) {
        const int s = kc % NSTG;
        CP_WAIT(NSTG - 2);
        __syncthreads();
        const int kl = kc + NSTG - 1;
        if (kl < KC) load_stage(kl, kl % NSTG);
        CP_COMMIT();

        if (kc == KHALF) {   // pass boundary: acc = acc * 128
#pragma unroll
            for (int i = 0; i < 4; i++)
#pragma unroll
                for (int j = 0; j < 4; j++)
#pragma unroll
                    for (int q = 0; q < 4; q++) c[i][j][q] <<= 7;
        }

#pragma unroll
        for (int ks = 0; ks < 2; ks++) {   // 2 x k32 steps
            uint32_t a[4][4];
#pragma unroll
            for (int mi = 0; mi < 4; mi++) {
                int row = wm + mi * 16 + (lane & 15);
                int colb = ks * 32 + (lane >> 4) * 16;
                ldm_x4(a[mi][0], a[mi][1], a[mi][2], a[mi][3],
                       sbA + (uint32_t)(s * STG_B + row * PKB + colb));
            }
            uint32_t b[4][2];
#pragma unroll
            for (int ni = 0; ni < 2; ni++) {
                int row = wn + ni * 16 + (lane & 7) + ((lane >> 4) << 3);
                int colb = ks * 32 + ((lane >> 3) & 1) * 16;
                uint32_t r0, r1, r2, r3;
                ldm_x4(r0, r1, r2, r3, sbB + (uint32_t)(s * STG_B + row * PKB + colb));
                b[ni * 2 + 0][0] = r0; b[ni * 2 + 0][1] = r1;
                b[ni * 2 + 1][0] = r2; b[ni * 2 + 1][1] = r3;
            }
#pragma unroll
            for (int mi = 0; mi < 4; mi++)
#pragma unroll
                for (int nj = 0; nj < 4; nj++)
                    mma_s8(c[mi][nj], a[mi], b[nj][0], b[nj][1]);
        }
    }

    // epilogue: dequant
    const int gr = lane >> 2;
    const int gc = (lane & 3) * 2;
#pragma unroll
    for (int mi = 0; mi < 4; mi++) {
        int m = m0 + wm + mi * 16 + gr;
        float sa0 = __ldg(&sA[m]);
        float sa1 = __ldg(&sA[m + 8]);
#pragma unroll
        for (int nj = 0; nj < 4; nj++) {
            int n = n0 + wn + nj * 8 + gc;
            float w0 = __ldg(&wscale[n]);
            float w1 = __ldg(&wscale[n + 1]);
            float2 v0 = {(float)c[mi][nj][0] * sa0 * w0, (float)c[mi][nj][1] * sa0 * w1};
            float2 v1 = {(float)c[mi][nj][2] * sa1 * w0, (float)c[mi][nj][3] * sa1 * w1};
            *(float2*)&out[(size_t)m * Ndim + n] = v0;
            *(float2*)&out[(size_t)(m + 8) * Ndim + n] = v1;
        }
    }
}

// ===================== conversions / quantization =====================
__global__ __launch_bounds__(256) void conv_w8_kernel(const int* __restrict__ W,
                                                      int8_t* __restrict__ O, int n4)
{
    int i = blockIdx.x * blockDim.x + threadIdx.x;
    if (i >= n4) return;
    int4 w = ((const int4*)W)[i];
    uint32_t p = (uint32_t)(w.x & 0xff) | ((uint32_t)(w.y & 0xff) << 8) |
                 ((uint32_t)(w.z & 0xff) << 16) | ((uint32_t)(w.w & 0xff) << 24);
    ((uint32_t*)O)[i] = p;
}

// per-row 2-digit base-128 quantization: x ~= S[row]*(128*X1 + X2)
__global__ __launch_bounds__(256) void quant_rows(
    const float* __restrict__ X, int8_t* __restrict__ X1, int8_t* __restrict__ X2,
    float* __restrict__ S, int K)
{
    const int row = blockIdx.x;
    const int tid = threadIdx.x;
    const float* xr = X + (size_t)row * K;
    float mx = 0.0f;
    for (int i = tid * 4; i < K; i += 1024) {
        float4 v = *(const float4*)(xr + i);
        mx = fmaxf(mx, fmaxf(fmaxf(fabsf(v.x), fabsf(v.y)), fmaxf(fabsf(v.z), fabsf(v.w))));
    }
#pragma unroll
    for (int o = 16; o > 0; o >>= 1) mx = fmaxf(mx, __shfl_xor_sync(0xffffffffu, mx, o));
    __shared__ float wm[8];
    if ((tid & 31) == 0) wm[tid >> 5] = mx;
    __syncthreads();
    float m = fmaxf(fmaxf(fmaxf(wm[0], wm[1]), fmaxf(wm[2], wm[3])),
                    fmaxf(fmaxf(wm[4], wm[5]), fmaxf(wm[6], wm[7])));
    float inv = (m > 0.0f) ? 16256.0f / m : 0.0f;
    if (tid == 0) S[row] = (m > 0.0f) ? m / 16256.0f : 0.0f;

    for (int i = tid * 4; i < K; i += 1024) {
        float4 v = *(const float4*)(xr + i);
        float vv[4] = {v.x, v.y, v.z, v.w};
        uint32_t p1 = 0, p2 = 0;
#pragma unroll
        for (int j = 0; j < 4; j++) {
            float t = vv[j] * inv;
            float h = rintf(t * 0.0078125f);
            h = fminf(fmaxf(h, -127.0f), 127.0f);
            float l = rintf(t - 128.0f * h);
            l = fminf(fmaxf(l, -127.0f), 127.0f);
            p1 |= ((uint32_t)((int)h & 0xff)) << (j * 8);
            p2 |= ((uint32_t)((int)l & 0xff)) << (j * 8);
        }
        *(uint32_t*)(X1 + (size_t)row * K + i) = p1;
        *(uint32_t*)(X2 + (size_t)row * K + i) = p2;
    }
}

// ===================== split + L2 norm -> bf16 hi/lo =====================
__global__ __launch_bounds__(256) void split_norm_kernel(
    const float* __restrict__ qkv, const float* __restrict__ gain_p,
    __nv_bfloat16* __restrict__ qhi, __nv_bfloat16* __restrict__ qlo,
    __nv_bfloat16* __restrict__ khi, __nv_bfloat16* __restrict__ klo,
    __nv_bfloat16* __restrict__ vhi, __nv_bfloat16* __restrict__ vlo)
{
    int gw = (blockIdx.x * blockDim.x + threadIdx.x) >> 5;
    int lane = threadIdx.x & 31;
    int which = gw / (BB * TT * NHH);
    int rem = gw % (BB * TT * NHH);
    int b = rem / (TT * NHH);
    int rem2 = rem % (TT * NHH);
    int t = rem2 / NHH;
    int h = rem2 % NHH;

    const float* src = qkv + (size_t)(b * TT + t) * THREEC + which * CC + h * HDD + lane * 4;
    float4 x = *(const float4*)src;

    if (which != 2) {
        float ss = x.x * x.x + x.y * x.y + x.z * x.z + x.w * x.w;
#pragma unroll
        for (int o = 16; o > 0; o >>= 1) ss += __shfl_xor_sync(0xffffffffu, ss, o);
        float n = sqrtf(ss);
        float s = gain_p[0] / fmaxf(n, 1e-12f);
        x.x *= s; x.y *= s; x.z *= s; x.w *= s;
    }

    __nv_bfloat16* HI = (which == 0) ? qhi : (which == 1) ? khi : vhi;
    __nv_bfloat16* LO = (which == 0) ? qlo : (which == 1) ? klo : vlo;
    size_t base = ((size_t)(b * NHH + h) * TT + t) * HDD + lane * 4;

    float xv[4] = {x.x, x.y, x.z, x.w};
    __nv_bfloat16 hh[4], ll[4];
#pragma unroll
    for (int i = 0; i < 4; i++) {
        hh[i] = __float2bfloat16_rn(xv[i]);
        ll[i] = __float2bfloat16_rn(xv[i] - __bfloat162float(hh[i]));
    }
    *(uint2*)&HI[base] = *(uint2*)hh;
    *(uint2*)&LO[base] = *(uint2*)ll;
}

// ===================== HMMA flash attention =====================
#define FPH 136
#define FQHI 0
#define FQLO (64*FPH)
#define FKHI (2*64*FPH)
#define FKLO (3*64*FPH)
#define FVHI (4*64*FPH)
#define FVLO (5*64*FPH)
#define FLASH_SMEM (6*64*FPH*2)

__global__ __launch_bounds__(128) void flash_mma_kernel(
    const __nv_bfloat16* __restrict__ Qhi, const __nv_bfloat16* __restrict__ Qlo,
    const __nv_bfloat16* __restrict__ Khi, const __nv_bfloat16* __restrict__ Klo,
    const __nv_bfloat16* __restrict__ Vhi, const __nv_bfloat16* __restrict__ Vlo,
    float* __restrict__ Y)
{
    extern __shared__ __nv_bfloat16 fsm[];
    const uint32_t sb = smem_u32(fsm);
    const int tid = threadIdx.x, lane = tid & 31, wid = tid >> 5;
    const int wr = wid * 16;
    const int qb = blockIdx.x, bh = blockIdx.y;
    const int q0 = qb * 64;
    const float SCALE = 0.08838834764831845f;

    const size_t bhoff = (size_t)bh * TT * HDD;
    const __nv_bfloat16* Qh = Qhi + bhoff;
    const __nv_bfloat16* Ql = Qlo + bhoff;
    const __nv_bfloat16* Kh = Khi + bhoff;
    const __nv_bfloat16* Kl = Klo + bhoff;
    const __nv_bfloat16* Vh = Vhi + bhoff;
    const __nv_bfloat16* Vl = Vlo + bhoff;

    {
        const int row = tid >> 1;
        const int c = (tid & 1) * 64;
#pragma unroll
        for (int q8 = 0; q8 < 64; q8 += 8) {
            uint4 vh_ = *(const uint4*)(Qh + (size_t)(q0 + row) * HDD + c + q8);
            uint4 vl_ = *(const uint4*)(Ql + (size_t)(q0 + row) * HDD + c + q8);
            uint32_t so = (row * FPH + c + q8) * 2;
            *(uint2*)((char*)fsm + FQHI * 2 + so)     = make_uint2(vh_.x, vh_.y);
            *(uint2*)((char*)fsm + FQHI * 2 + so + 8) = make_uint2(vh_.z, vh_.w);
            *(uint2*)((char*)fsm + FQLO * 2 + so)     = make_uint2(vl_.x, vl_.y);
            *(uint2*)((char*)fsm + FQLO * 2 + so + 8) = make_uint2(vl_.z, vl_.w);
        }
    }

    float o[16][4];
#pragma unroll
    for (int i = 0; i < 16; i++)
#pragma unroll
        for (int j = 0; j < 4; j++) o[i][j] = 0.0f;
    float m0v = -1e30f, m1v = -1e30f, l0 = 0.0f, l1 = 0.0f;

    for (int jb = 0; jb <= qb; jb++) {
        const int k0 = jb * 64;
        __syncthreads();
        {
            const int row = tid >> 1;
            const int c = (tid & 1) * 64;
#pragma unroll
            for (int q8 = 0; q8 < 64; q8 += 8) {
                uint32_t so = (row * FPH + c + q8) * 2;
                uint4 a0 = *(const uint4*)(Kh + (size_t)(k0 + row) * HDD + c + q8);
                *(uint2*)((char*)fsm + FKHI * 2 + so)     = make_uint2(a0.x, a0.y);
                *(uint2*)((char*)fsm + FKHI * 2 + so + 8) = make_uint2(a0.z, a0.w);
                uint4 a1 = *(const uint4*)(Kl + (size_t)(k0 + row) * HDD + c + q8);
                *(uint2*)((char*)fsm + FKLO * 2 + so)     = make_uint2(a1.x, a1.y);
                *(uint2*)((char*)fsm + FKLO * 2 + so + 8) = make_uint2(a1.z, a1.w);
                uint4 a2 = *(const uint4*)(Vh + (size_t)(k0 + row) * HDD + c + q8);
                *(uint2*)((char*)fsm + FVHI * 2 + so)     = make_uint2(a2.x, a2.y);
                *(uint2*)((char*)fsm + FVHI * 2 + so + 8) = make_uint2(a2.z, a2.w);
                uint4 a3 = *(const uint4*)(Vl + (size_t)(k0 + row) * HDD + c + q8);
                *(uint2*)((char*)fsm + FVLO * 2 + so)     = make_uint2(a3.x, a3.y);
                *(uint2*)((char*)fsm + FVLO * 2 + so + 8) = make_uint2(a3.z, a3.w);
            }
        }
        __syncthreads();

        float s[8][4];
#pragma unroll
        for (int i = 0; i < 8; i++)
#pragma unroll
            for (int j = 0; j < 4; j++) s[i][j] = 0.0f;

#pragma unroll
        for (int ks = 0; ks < 8; ks++) {
            uint32_t ah[4], al[4];
            uint32_t qoff = sb + (uint32_t)((wr + (lane & 15)) * FPH + ks * 16 + (lane >> 4) * 8) * 2;
            ldm_x4(ah[0], ah[1], ah[2], ah[3], qoff + FQHI * 2);
            ldm_x4(al[0], al[1], al[2], al[3], qoff + FQLO * 2);
#pragma unroll
            for (int nt2 = 0; nt2 < 4; nt2++) {
                uint32_t koff = sb + (uint32_t)((nt2 * 16 + (lane & 7) + ((lane >> 4) << 3)) * FPH
                                                + ks * 16 + ((lane >> 3) & 1) * 8) * 2;
                uint32_t bh0, bh1, bh2, bh3, bl0, bl1, bl2, bl3;
                ldm_x4(bh0, bh1, bh2, bh3, koff + FKHI * 2);
                ldm_x4(bl0, bl1, bl2, bl3, koff + FKLO * 2);
                mma_bf16(s[nt2 * 2 + 0], ah, bh0, bh1);
                mma_bf16(s[nt2 * 2 + 1], ah, bh2, bh3);
                mma_bf16(s[nt2 * 2 + 0], ah, bl0, bl1);
                mma_bf16(s[nt2 * 2 + 1], ah, bl2, bl3);
                mma_bf16(s[nt2 * 2 + 0], al, bh0, bh1);
                mma_bf16(s[nt2 * 2 + 1], al, bh2, bh3);
            }
        }

        const int lr0 = wr + (lane >> 2);
        const int lc0 = (lane & 3) * 2;
#pragma unroll
        for (int nt = 0; nt < 8; nt++) {
#pragma unroll
            for (int j = 0; j < 4; j++) s[nt][j] *= SCALE;
            if (jb == qb) {
                int col = nt * 8 + lc0;
                if (col > lr0)     s[nt][0] = -1e30f;
                if (col + 1 > lr0) s[nt][1] = -1e30f;
                if (col > lr0 + 8)     s[nt][2] = -1e30f;
                if (col + 1 > lr0 + 8) s[nt][3] = -1e30f;
            }
        }

        float rm0 = -1e30f, rm1 = -1e30f;
#pragma unroll
        for (int nt = 0; nt < 8; nt++) {
            rm0 = fmaxf(rm0, fmaxf(s[nt][0], s[nt][1]));
            rm1 = fmaxf(rm1, fmaxf(s[nt][2], s[nt][3]));
        }
        rm0 = fmaxf(rm0, __shfl_xor_sync(0xffffffffu, rm0, 1));
        rm0 = fmaxf(rm0, __shfl_xor_sync(0xffffffffu, rm0, 2));
        rm1 = fmaxf(rm1, __shfl_xor_sync(0xffffffffu, rm1, 1));
        rm1 = fmaxf(rm1, __shfl_xor_sync(0xffffffffu, rm1, 2));
        float mn0 = fmaxf(m0v, rm0), mn1 = fmaxf(m1v, rm1);
        float cor0 = __expf(m0v - mn0), cor1 = __expf(m1v - mn1);
        float sum0 = 0.0f, sum1 = 0.0f;
        uint32_t phi[4][4], plo[4][4];
#pragma unroll
        for (int nt = 0; nt < 8; nt++) {
            float p0 = __expf(s[nt][0] - mn0);
            float p1 = __expf(s[nt][1] - mn0);
            float p2 = __expf(s[nt][2] - mn1);
            float p3 = __expf(s[nt][3] - mn1);
            sum0 += p0 + p1; sum1 += p2 + p3;
            __nv_bfloat16 h0 = __float2bfloat16_rn(p0), h1 = __float2bfloat16_rn(p1);
            __nv_bfloat16 h2 = __float2bfloat16_rn(p2), h3 = __float2bfloat16_rn(p3);
            __nv_bfloat16 e0 = __float2bfloat16_rn(p0 - __bfloat162float(h0));
            __nv_bfloat16 e1 = __float2bfloat16_rn(p1 - __bfloat162float(h1));
            __nv_bfloat16 e2 = __float2bfloat16_rn(p2 - __bfloat162float(h2));
            __nv_bfloat16 e3 = __float2bfloat16_rn(p3 - __bfloat162float(h3));
            int ks = nt >> 1;
            int hi2 = nt & 1;
            __nv_bfloat162 ph01 = {h0, h1}, ph23 = {h2, h3};
            __nv_bfloat162 pl01 = {e0, e1}, pl23 = {e2, e3};
            phi[ks][hi2 * 2 + 0] = *(uint32_t*)&ph01;
            phi[ks][hi2 * 2 + 1] = *(uint32_t*)&ph23;
            plo[ks][hi2 * 2 + 0] = *(uint32_t*)&pl01;
            plo[ks][hi2 * 2 + 1] = *(uint32_t*)&pl23;
        }
        sum0 += __shfl_xor_sync(0xffffffffu, sum0, 1);
        sum0 += __shfl_xor_sync(0xffffffffu, sum0, 2);
        sum1 += __shfl_xor_sync(0xffffffffu, sum1, 1);
        sum1 += __shfl_xor_sync(0xffffffffu, sum1, 2);
        l0 = l0 * cor0 + sum0;
        l1 = l1 * cor1 + sum1;
        m0v = mn0; m1v = mn1;
#pragma unroll
        for (int nt = 0; nt < 16; nt++) {
            o[nt][0] *= cor0; o[nt][1] *= cor0;
            o[nt][2] *= cor1; o[nt][3] *= cor1;
        }

#pragma unroll
        for (int pass = 0; pass < 3; pass++) {
            const uint32_t vbase = (pass == 1) ? FVLO * 2 : FVHI * 2;
            uint32_t (*pf)[4] = (pass == 2) ? plo : phi;
#pragma unroll
            for (int ks = 0; ks < 4; ks++) {
#pragma unroll
                for (int nt2 = 0; nt2 < 8; nt2++) {
                    uint32_t voff = sb + vbase +
                        (uint32_t)((ks * 16 + (lane & 15)) * FPH + nt2 * 16 + (lane >> 4) * 8) * 2;
                    uint32_t b0, b1, b2, b3;
                    ldm_x4_t(b0, b1, b2, b3, voff);
                    mma_bf16(o[nt2 * 2 + 0], pf[ks], b0, b1);
                    mma_bf16(o[nt2 * 2 + 1], pf[ks], b2, b3);
                }
            }
        }
    }

    // epilogue: y = O/l (fp32) to [B,T,C]
    const int b = bh / NHH, h = bh % NHH;
    const int r0 = wr + (lane >> 2);
    const int cbase = (lane & 3) * 2;
    float inv0 = 1.0f / l0, inv1 = 1.0f / l1;
    size_t rowA = (size_t)(b * TT + q0 + r0) * CC + h * HDD;
    size_t rowB = (size_t)(b * TT + q0 + r0 + 8) * CC + h * HDD;
#pragma unroll
    for (int nt = 0; nt < 16; nt++) {
        int col = nt * 8 + cbase;
        float2 vA = {o[nt][0] * inv0, o[nt][1] * inv0};
        float2 vB = {o[nt][2] * inv1, o[nt][3] * inv1};
        *(float2*)&Y[rowA + col] = vA;
        *(float2*)&Y[rowB + col] = vB;
    }
}

// ===================== launch =====================
extern "C" void kernel_launch(void* const* d_in, const int* in_sizes, int n_in,
                              void* d_out, int out_size)
{
    const float* x           = (const float*)d_in[0];
    const int*   attn_w      = (const int*)d_in[1];
    const float* attn_scales = (const float*)d_in[2];
    const int*   proj_w      = (const int*)d_in[3];
    const float* proj_scales = (const float*)d_in[4];
    const float* qk_gain     = (const float*)d_in[5];
    float* out = (float*)d_out;

    float *p_qkv, *p_y, *p_sx, *p_sy;
    int8_t *p_w8a, *p_w8p, *p_x1, *p_x2, *p_y1, *p_y2;
    __nv_bfloat16 *p_qhi, *p_qlo, *p_khi, *p_klo, *p_vhi, *p_vlo;
    cudaGetSymbolAddress((void**)&p_qkv, g_qkv);
    cudaGetSymbolAddress((void**)&p_y,   g_y);
    cudaGetSymbolAddress((void**)&p_sx,  g_sx);
    cudaGetSymbolAddress((void**)&p_sy,  g_sy);
    cudaGetSymbolAddress((void**)&p_w8a, g_w8a);
    cudaGetSymbolAddress((void**)&p_w8p, g_w8p);
    cudaGetSymbolAddress((void**)&p_x1,  g_x1);
    cudaGetSymbolAddress((void**)&p_x2,  g_x2);
    cudaGetSymbolAddress((void**)&p_y1,  g_y1);
    cudaGetSymbolAddress((void**)&p_y2,  g_y2);
    cudaGetSymbolAddress((void**)&p_qhi, g_qhi);
    cudaGetSymbolAddress((void**)&p_qlo, g_qlo);
    cudaGetSymbolAddress((void**)&p_khi, g_khi);
    cudaGetSymbolAddress((void**)&p_klo, g_klo);
    cudaGetSymbolAddress((void**)&p_vhi, g_vhi);
    cudaGetSymbolAddress((void**)&p_vlo, g_vlo);

    cudaFuncSetAttribute(gemm_imma, cudaFuncAttributeMaxDynamicSharedMemorySize, GEMM_SMEM);
    cudaFuncSetAttribute(flash_mma_kernel, cudaFuncAttributeMaxDynamicSharedMemorySize, FLASH_SMEM);

    // 0) weight conversions (int32 -> int8, exact)
    conv_w8_kernel<<<(THREEC * CC / 4 + 255) / 256, 256>>>(attn_w, p_w8a, THREEC * CC / 4);
    conv_w8_kernel<<<(CC * CC / 4 + 255) / 256, 256>>>(proj_w, p_w8p, CC * CC / 4);

    // 1) quantize x per-row (2-digit base-128)
    quant_rows<<<MTOK, 256>>>(x, p_x1, p_x2, p_sx, CC);

    // 2) QKV = x @ Wa^T  (IMMA)
    gemm_imma<<<dim3(THREEC / BN, MTOK / BM), 256, GEMM_SMEM>>>(
        p_x1, p_x2, p_w8a, p_sx, attn_scales, p_qkv, THREEC, CC);

    // 3) split + L2 norm -> bf16 hi/lo q/k/v
    split_norm_kernel<<<3 * BB * TT * NHH / 8, 256>>>(
        p_qkv, qk_gain, p_qhi, p_qlo, p_khi, p_klo, p_vhi, p_vlo);

    // 4) HMMA flash attention -> y (fp32)
    flash_mma_kernel<<<dim3(TT / 64, BB * NHH), 128, FLASH_SMEM>>>(
        p_qhi, p_qlo, p_khi, p_klo, p_vhi, p_vlo, p_y);

    // 5) quantize y per-row
    quant_rows<<<MTOK, 256>>>(p_y, p_y1, p_y2, p_sy, CC);

    // 6) out = y @ Wp^T  (IMMA)
    gemm_imma<<<dim3(CC / BN, MTOK / BM), 256, GEMM_SMEM>>>(
        p_y1, p_y2, p_w8p, p_sy, proj_scales, out, CC, CC);
}

// round 7
// speedup vs baseline: 3.1331x; 3.1331x over previous
#include <cuda_runtime.h>
#include <cuda_fp16.h>
#include <stdint.h>
#include <math.h>

// Problem constants
#define BB 2
#define TT 2048
#define CC 2048
#define NHH 16
#define HDD 128
#define MTOK (BB*TT)        // 4096
#define THREEC (3*CC)       // 6144

// ---------------- scratch (device globals) ----------------
__device__ float  g_qkv[(size_t)MTOK * THREEC];
__device__ __half g_wha[(size_t)THREEC * CC];
__device__ __half g_whp[(size_t)CC * CC];
__device__ __half g_xh[(size_t)MTOK * CC];
__device__ __half g_qh[(size_t)BB*NHH*TT*HDD];
__device__ __half g_kh[(size_t)BB*NHH*TT*HDD];
__device__ __half g_vh[(size_t)BB*NHH*TT*HDD];
__device__ __half g_yh[(size_t)MTOK * CC];

// ===================== helpers =====================
__device__ __forceinline__ uint32_t smem_u32(const void* p) {
    uint32_t a;
    asm("{ .reg .u64 t; cvta.to.shared.u64 t, %1; cvt.u32.u64 %0, t; }" : "=r"(a) : "l"(p));
    return a;
}
#define CP_ASYNC16(s, g) asm volatile("cp.async.cg.shared.global [%0], [%1], 16;" :: "r"(s), "l"(g))
#define CP_COMMIT()      asm volatile("cp.async.commit_group;" ::: "memory")
#define CP_WAIT(n)       asm volatile("cp.async.wait_group %0;" :: "n"(n) : "memory")

__device__ __forceinline__ void ldm_x4(uint32_t& r0, uint32_t& r1, uint32_t& r2, uint32_t& r3,
                                       uint32_t addr) {
    asm volatile("ldmatrix.sync.aligned.m8n8.x4.shared.b16 {%0,%1,%2,%3}, [%4];"
                 : "=r"(r0), "=r"(r1), "=r"(r2), "=r"(r3) : "r"(addr));
}
__device__ __forceinline__ void ldm_x4_t(uint32_t& r0, uint32_t& r1, uint32_t& r2, uint32_t& r3,
                                         uint32_t addr) {
    asm volatile("ldmatrix.sync.aligned.m8n8.x4.trans.shared.b16 {%0,%1,%2,%3}, [%4];"
                 : "=r"(r0), "=r"(r1), "=r"(r2), "=r"(r3) : "r"(addr));
}
__device__ __forceinline__ void mma_f16(float* c, const uint32_t* a, uint32_t b0, uint32_t b1) {
    asm volatile(
        "mma.sync.aligned.m16n8k16.row.col.f32.f16.f16.f32 "
        "{%0,%1,%2,%3}, {%4,%5,%6,%7}, {%8,%9}, {%0,%1,%2,%3};"
        : "+f"(c[0]), "+f"(c[1]), "+f"(c[2]), "+f"(c[3])
        : "r"(a[0]), "r"(a[1]), "r"(a[2]), "r"(a[3]), "r"(b0), "r"(b1));
}

// ===================== fp16 HMMA weight GEMM =====================
// out[m,n] = scales[n] * sum_k A[m,k] * W[n,k]   (fp16 in, fp32 accum)
// 128x128 tile, K chunk 32, 8 warps (2x4), 4-stage cp.async pipeline.
#define BM 128
#define BN 128
#define BKK 32
#define PKH 40                        // halves pitch
#define STG_H (BM * PKH)              // 5120 halves
#define NSTG 4
#define GEMM_SMEM (NSTG * STG_H * 2 * 2)   // 81920 bytes

__global__ __launch_bounds__(256) void gemm_mma_f16(
    const __half* __restrict__ A, const __half* __restrict__ Wb,
    const float* __restrict__ scales, float* __restrict__ out, int Ndim, int Kdim)
{
    extern __shared__ __half smg[];
    const uint32_t sbA = smem_u32(smg);
    const uint32_t sbB = sbA + NSTG * STG_H * 2;

    const int tid = threadIdx.x, lane = tid & 31, wid = tid >> 5;
    const int wm = (wid >> 2) * 64;
    const int wn = (wid & 3) * 32;
    const int m0 = blockIdx.y * BM;
    const int n0 = blockIdx.x * BN;
    const int KC = Kdim >> 5;         // 32-half chunks

    float c[4][4][4];
#pragma unroll
    for (int i = 0; i < 4; i++)
#pragma unroll
        for (int j = 0; j < 4; j++)
#pragma unroll
            for (int q = 0; q < 4; q++) c[i][j][q] = 0.0f;

    const int lr = tid >> 2;
    const int lq = (tid & 3) * 8;

    auto load_stage = [&](int kc, int s) {
        const int k0 = kc << 5;
#pragma unroll
        for (int half = 0; half < 2; half++) {
            int r = lr + half * 64;
            CP_ASYNC16(sbA + (uint32_t)(s * STG_H + r * PKH + lq) * 2,
                       A + (size_t)(m0 + r) * Kdim + k0 + lq);
            CP_ASYNC16(sbB + (uint32_t)(s * STG_H + r * PKH + lq) * 2,
                       Wb + (size_t)(n0 + r) * Kdim + k0 + lq);
        }
    };

#pragma unroll
    for (int s = 0; s < NSTG - 1; s++) { load_stage(s, s); CP_COMMIT(); }

    for (int kc = 0; kc < KC; kc++) {
        const int s = kc % NSTG;
        CP_WAIT(NSTG - 2);
        __syncthreads();
        const int kl = kc + NSTG - 1;
        if (kl < KC) load_stage(kl, kl % NSTG);
        CP_COMMIT();

#pragma unroll
        for (int ks = 0; ks < 2; ks++) {
            uint32_t a[4][4];
#pragma unroll
            for (int mi = 0; mi < 4; mi++) {
                int row = wm + mi * 16 + (lane & 15);
                int col = ks * 16 + (lane >> 4) * 8;
                ldm_x4(a[mi][0], a[mi][1], a[mi][2], a[mi][3],
                       sbA + (uint32_t)(s * STG_H + row * PKH + col) * 2);
            }
            uint32_t b[4][2];
#pragma unroll
            for (int ni = 0; ni < 2; ni++) {
                int row = wn + ni * 16 + (lane & 7) + ((lane >> 4) << 3);
                int col = ks * 16 + ((lane >> 3) & 1) * 8;
                uint32_t r0, r1, r2, r3;
                ldm_x4(r0, r1, r2, r3, sbB + (uint32_t)(s * STG_H + row * PKH + col) * 2);
                b[ni * 2 + 0][0] = r0; b[ni * 2 + 0][1] = r1;
                b[ni * 2 + 1][0] = r2; b[ni * 2 + 1][1] = r3;
            }
#pragma unroll
            for (int mi = 0; mi < 4; mi++)
#pragma unroll
                for (int nj = 0; nj < 4; nj++)
                    mma_f16(c[mi][nj], a[mi], b[nj][0], b[nj][1]);
        }
    }

    const int gr = lane >> 2;
    const int gc = (lane & 3) * 2;
#pragma unroll
    for (int mi = 0; mi < 4; mi++) {
#pragma unroll
        for (int nj = 0; nj < 4; nj++) {
            int m = m0 + wm + mi * 16 + gr;
            int n = n0 + wn + nj * 8 + gc;
            float s0 = __ldg(&scales[n]);
            float s1 = __ldg(&scales[n + 1]);
            float2 v0 = {c[mi][nj][0] * s0, c[mi][nj][1] * s1};
            float2 v1 = {c[mi][nj][2] * s0, c[mi][nj][3] * s1};
            *(float2*)&out[(size_t)m * Ndim + n] = v0;
            *(float2*)&out[(size_t)(m + 8) * Ndim + n] = v1;
        }
    }
}

// ===================== conversions =====================
__global__ __launch_bounds__(256) void conv_w_kernel(const int* __restrict__ W,
                                                     __half* __restrict__ O, int n4)
{
    int i = blockIdx.x * blockDim.x + threadIdx.x;
    if (i >= n4) return;
    int4 w = ((const int4*)W)[i];
    __half o[4] = { __int2half_rn(w.x), __int2half_rn(w.y),
                    __int2half_rn(w.z), __int2half_rn(w.w) };
    ((uint2*)O)[i] = *(uint2*)o;
}

__global__ __launch_bounds__(256) void conv_x_kernel(const float* __restrict__ X,
                                                     __half* __restrict__ O, int n4)
{
    int i = blockIdx.x * blockDim.x + threadIdx.x;
    if (i >= n4) return;
    float4 v = ((const float4*)X)[i];
    __half o[4] = { __float2half_rn(v.x), __float2half_rn(v.y),
                    __float2half_rn(v.z), __float2half_rn(v.w) };
    ((uint2*)O)[i] = *(uint2*)o;
}

// ===================== split + L2 norm -> fp16 =====================
__global__ __launch_bounds__(256) void split_norm_kernel(
    const float* __restrict__ qkv, const float* __restrict__ gain_p,
    __half* __restrict__ q, __half* __restrict__ k, __half* __restrict__ v)
{
    int gw = (blockIdx.x * blockDim.x + threadIdx.x) >> 5;
    int lane = threadIdx.x & 31;
    int which = gw / (BB * TT * NHH);
    int rem = gw % (BB * TT * NHH);
    int b = rem / (TT * NHH);
    int rem2 = rem % (TT * NHH);
    int t = rem2 / NHH;
    int h = rem2 % NHH;

    const float* src = qkv + (size_t)(b * TT + t) * THREEC + which * CC + h * HDD + lane * 4;
    float4 x = *(const float4*)src;

    if (which != 2) {
        float ss = x.x * x.x + x.y * x.y + x.z * x.z + x.w * x.w;
#pragma unroll
        for (int o = 16; o > 0; o >>= 1) ss += __shfl_xor_sync(0xffffffffu, ss, o);
        float n = sqrtf(ss);
        float s = gain_p[0] / fmaxf(n, 1e-12f);
        x.x *= s; x.y *= s; x.z *= s; x.w *= s;
    }

    __half* dst = (which == 0) ? q : (which == 1) ? k : v;
    size_t base = ((size_t)(b * NHH + h) * TT + t) * HDD + lane * 4;
    __half o[4] = { __float2half_rn(x.x), __float2half_rn(x.y),
                    __float2half_rn(x.z), __float2half_rn(x.w) };
    *(uint2*)&dst[base] = *(uint2*)o;
}

// ===================== fp16 HMMA flash attention =====================
// Block: 64 q-rows, 128 threads (4 warps), 64 keys/iter, single-pass fp16.
#define FPH 136
#define FQ 0
#define FK (64*FPH)
#define FV (2*64*FPH)
#define FLASH_SMEM (3*64*FPH*2)    // 52224 bytes

__global__ __launch_bounds__(128) void flash_mma_kernel(
    const __half* __restrict__ Qg, const __half* __restrict__ Kg,
    const __half* __restrict__ Vg, __half* __restrict__ Yh)
{
    extern __shared__ __half fsm[];
    const uint32_t sb = smem_u32(fsm);
    const int tid = threadIdx.x, lane = tid & 31, wid = tid >> 5;
    const int wr = wid * 16;
    const int qb = blockIdx.x, bh = blockIdx.y;
    const int q0 = qb * 64;
    const float SCALE = 0.08838834764831845f;

    const size_t bhoff = (size_t)bh * TT * HDD;
    const __half* Qb = Qg + bhoff;
    const __half* Kb = Kg + bhoff;
    const __half* Vb = Vg + bhoff;

    // load Q tile (64x128)
    {
        const int row = tid >> 1;
        const int c = (tid & 1) * 64;
#pragma unroll
        for (int q8 = 0; q8 < 64; q8 += 8) {
            uint4 qv = *(const uint4*)(Qb + (size_t)(q0 + row) * HDD + c + q8);
            uint32_t so = (row * FPH + c + q8) * 2;
            *(uint2*)((char*)fsm + FQ * 2 + so)     = make_uint2(qv.x, qv.y);
            *(uint2*)((char*)fsm + FQ * 2 + so + 8) = make_uint2(qv.z, qv.w);
        }
    }

    float o[16][4];
#pragma unroll
    for (int i = 0; i < 16; i++)
#pragma unroll
        for (int j = 0; j < 4; j++) o[i][j] = 0.0f;
    float m0v = -1e30f, m1v = -1e30f, l0 = 0.0f, l1 = 0.0f;

    for (int jb = 0; jb <= qb; jb++) {
        const int k0 = jb * 64;
        __syncthreads();
        {
            const int row = tid >> 1;
            const int c = (tid & 1) * 64;
#pragma unroll
            for (int q8 = 0; q8 < 64; q8 += 8) {
                uint32_t so = (row * FPH + c + q8) * 2;
                uint4 a0 = *(const uint4*)(Kb + (size_t)(k0 + row) * HDD + c + q8);
                *(uint2*)((char*)fsm + FK * 2 + so)     = make_uint2(a0.x, a0.y);
                *(uint2*)((char*)fsm + FK * 2 + so + 8) = make_uint2(a0.z, a0.w);
                uint4 a2 = *(const uint4*)(Vb + (size_t)(k0 + row) * HDD + c + q8);
                *(uint2*)((char*)fsm + FV * 2 + so)     = make_uint2(a2.x, a2.y);
                *(uint2*)((char*)fsm + FV * 2 + so + 8) = make_uint2(a2.z, a2.w);
            }
        }
        __syncthreads();

        // S = Q K^T
        float s[8][4];
#pragma unroll
        for (int i = 0; i < 8; i++)
#pragma unroll
            for (int j = 0; j < 4; j++) s[i][j] = 0.0f;

#pragma unroll
        for (int ks = 0; ks < 8; ks++) {
            uint32_t a[4];
            uint32_t qoff = sb + (uint32_t)((wr + (lane & 15)) * FPH + ks * 16 + (lane >> 4) * 8) * 2;
            ldm_x4(a[0], a[1], a[2], a[3], qoff + FQ * 2);
#pragma unroll
            for (int nt2 = 0; nt2 < 4; nt2++) {
                uint32_t koff = sb + (uint32_t)((nt2 * 16 + (lane & 7) + ((lane >> 4) << 3)) * FPH
                                                + ks * 16 + ((lane >> 3) & 1) * 8) * 2;
                uint32_t b0, b1, b2, b3;
                ldm_x4(b0, b1, b2, b3, koff + FK * 2);
                mma_f16(s[nt2 * 2 + 0], a, b0, b1);
                mma_f16(s[nt2 * 2 + 1], a, b2, b3);
            }
        }

        // scale + causal mask
        const int lr0 = wr + (lane >> 2);
        const int lc0 = (lane & 3) * 2;
#pragma unroll
        for (int nt = 0; nt < 8; nt++) {
#pragma unroll
            for (int j = 0; j < 4; j++) s[nt][j] *= SCALE;
            if (jb == qb) {
                int col = nt * 8 + lc0;
                if (col > lr0)     s[nt][0] = -1e30f;
                if (col + 1 > lr0) s[nt][1] = -1e30f;
                if (col > lr0 + 8)     s[nt][2] = -1e30f;
                if (col + 1 > lr0 + 8) s[nt][3] = -1e30f;
            }
        }

        // online softmax
        float rm0 = -1e30f, rm1 = -1e30f;
#pragma unroll
        for (int nt = 0; nt < 8; nt++) {
            rm0 = fmaxf(rm0, fmaxf(s[nt][0], s[nt][1]));
            rm1 = fmaxf(rm1, fmaxf(s[nt][2], s[nt][3]));
        }
        rm0 = fmaxf(rm0, __shfl_xor_sync(0xffffffffu, rm0, 1));
        rm0 = fmaxf(rm0, __shfl_xor_sync(0xffffffffu, rm0, 2));
        rm1 = fmaxf(rm1, __shfl_xor_sync(0xffffffffu, rm1, 1));
        rm1 = fmaxf(rm1, __shfl_xor_sync(0xffffffffu, rm1, 2));
        float mn0 = fmaxf(m0v, rm0), mn1 = fmaxf(m1v, rm1);
        float cor0 = __expf(m0v - mn0), cor1 = __expf(m1v - mn1);
        float sum0 = 0.0f, sum1 = 0.0f;
        uint32_t pf[4][4];
#pragma unroll
        for (int nt = 0; nt < 8; nt++) {
            float p0 = __expf(s[nt][0] - mn0);
            float p1 = __expf(s[nt][1] - mn0);
            float p2 = __expf(s[nt][2] - mn1);
            float p3 = __expf(s[nt][3] - mn1);
            sum0 += p0 + p1; sum1 += p2 + p3;
            __half2 ph01 = {__float2half_rn(p0), __float2half_rn(p1)};
            __half2 ph23 = {__float2half_rn(p2), __float2half_rn(p3)};
            int ks = nt >> 1;
            int hi2 = nt & 1;
            pf[ks][hi2 * 2 + 0] = *(uint32_t*)&ph01;
            pf[ks][hi2 * 2 + 1] = *(uint32_t*)&ph23;
        }
        sum0 += __shfl_xor_sync(0xffffffffu, sum0, 1);
        sum0 += __shfl_xor_sync(0xffffffffu, sum0, 2);
        sum1 += __shfl_xor_sync(0xffffffffu, sum1, 1);
        sum1 += __shfl_xor_sync(0xffffffffu, sum1, 2);
        l0 = l0 * cor0 + sum0;
        l1 = l1 * cor1 + sum1;
        m0v = mn0; m1v = mn1;
#pragma unroll
        for (int nt = 0; nt < 16; nt++) {
            o[nt][0] *= cor0; o[nt][1] *= cor0;
            o[nt][2] *= cor1; o[nt][3] *= cor1;
        }

        // O += P V
#pragma unroll
        for (int ks = 0; ks < 4; ks++) {
#pragma unroll
            for (int nt2 = 0; nt2 < 8; nt2++) {
                uint32_t voff = sb + FV * 2 +
                    (uint32_t)((ks * 16 + (lane & 15)) * FPH + nt2 * 16 + (lane >> 4) * 8) * 2;
                uint32_t b0, b1, b2, b3;
                ldm_x4_t(b0, b1, b2, b3, voff);
                mma_f16(o[nt2 * 2 + 0], pf[ks], b0, b1);
                mma_f16(o[nt2 * 2 + 1], pf[ks], b2, b3);
            }
        }
    }

    // epilogue: y = O/l -> fp16, write to [B,T,C]
    const int b = bh / NHH, h = bh % NHH;
    const int r0 = wr + (lane >> 2);
    const int cbase = (lane & 3) * 2;
    float inv0 = 1.0f / l0, inv1 = 1.0f / l1;
    size_t rowA = (size_t)(b * TT + q0 + r0) * CC + h * HDD;
    size_t rowB = (size_t)(b * TT + q0 + r0 + 8) * CC + h * HDD;
#pragma unroll
    for (int nt = 0; nt < 16; nt++) {
        int col = nt * 8 + cbase;
        __half2 vA = {__float2half_rn(o[nt][0] * inv0), __float2half_rn(o[nt][1] * inv0)};
        __half2 vB = {__float2half_rn(o[nt][2] * inv1), __float2half_rn(o[nt][3] * inv1)};
        *(uint32_t*)&Yh[rowA + col] = *(uint32_t*)&vA;
        *(uint32_t*)&Yh[rowB + col] = *(uint32_t*)&vB;
    }
}

// ===================== launch =====================
extern "C" void kernel_launch(void* const* d_in, const int* in_sizes, int n_in,
                              void* d_out, int out_size)
{
    const float* x           = (const float*)d_in[0];
    const int*   attn_w      = (const int*)d_in[1];
    const float* attn_scales = (const float*)d_in[2];
    const int*   proj_w      = (const int*)d_in[3];
    const float* proj_scales = (const float*)d_in[4];
    const float* qk_gain     = (const float*)d_in[5];
    float* out = (float*)d_out;

    float* p_qkv;
    __half *p_wha, *p_whp, *p_xh, *p_qh, *p_kh, *p_vh, *p_yh;
    cudaGetSymbolAddress((void**)&p_qkv, g_qkv);
    cudaGetSymbolAddress((void**)&p_wha, g_wha);
    cudaGetSymbolAddress((void**)&p_whp, g_whp);
    cudaGetSymbolAddress((void**)&p_xh,  g_xh);
    cudaGetSymbolAddress((void**)&p_qh,  g_qh);
    cudaGetSymbolAddress((void**)&p_kh,  g_kh);
    cudaGetSymbolAddress((void**)&p_vh,  g_vh);
    cudaGetSymbolAddress((void**)&p_yh,  g_yh);

    cudaFuncSetAttribute(gemm_mma_f16, cudaFuncAttributeMaxDynamicSharedMemorySize, GEMM_SMEM);
    cudaFuncSetAttribute(flash_mma_kernel, cudaFuncAttributeMaxDynamicSharedMemorySize, FLASH_SMEM);

    // 0) weight conversions (int32 -> fp16, exact)
    conv_w_kernel<<<(THREEC * CC / 4 + 255) / 256, 256>>>(attn_w, p_wha, THREEC * CC / 4);
    conv_w_kernel<<<(CC * CC / 4 + 255) / 256, 256>>>(proj_w, p_whp, CC * CC / 4);

    // 1) x -> fp16
    conv_x_kernel<<<(MTOK * CC / 4 + 255) / 256, 256>>>(x, p_xh, MTOK * CC / 4);

    // 2) QKV = x @ Wa^T
    gemm_mma_f16<<<dim3(THREEC / BN, MTOK / BM), 256, GEMM_SMEM>>>(
        p_xh, p_wha, attn_scales, p_qkv, THREEC, CC);

    // 3) split + L2 norm -> fp16 q/k/v
    split_norm_kernel<<<3 * BB * TT * NHH / 8, 256>>>(p_qkv, qk_gain, p_qh, p_kh, p_vh);

    // 4) fp16 HMMA flash attention -> yh
    flash_mma_kernel<<<dim3(TT / 64, BB * NHH), 128, FLASH_SMEM>>>(p_qh, p_kh, p_vh, p_yh);

    // 5) out = y @ Wp^T
    gemm_mma_f16<<<dim3(CC / BN, MTOK / BM), 256, GEMM_SMEM>>>(
        p_yh, p_whp, proj_scales, out, CC, CC);
}